// round 13
// baseline (speedup 1.0000x reference)
#include <cuda_runtime.h>
#include <cuda_bf16.h>
#include <cstdint>

#define NTHREADS 384
#define T        180
#define GRID_P   152
#define MAXN     2097152

typedef unsigned int u32;

// ---- W plane element offsets (bf16 elems) ----
#define PW2 0          // [40][112]  = 4480  (K = tap*20+ci, 100 real, 12 pad)
#define PW3 4480       // [80][40]   = 3200  (exact, no pad)
#define PW4 7680       // [40][84]   = 3360  (80 real + 4 pad for banks)
#define PW5 11040      // [3][24][40]= 2880
#define PLANE_ELEMS 13920

// ---- smem byte offsets ----
#define OWHI 0
#define OWLO (PLANE_ELEMS*2)            // 27840
#define OSC  (OWLO + PLANE_ELEMS*2)     // 55680 (f32 scalars)
#define SW1 0
#define SB1 100
#define SB2 120
#define SB3 160
#define SB4 240
#define SB5 280      // 24 (20 real + 4 zero)
#define SW6 304
#define SB6 324
// y1 flat: dense [192][20] bf16 (40B rows) with 128B zero guards both sides
#define OY1F_HI_G 57088
#define OY1F_HI   (OY1F_HI_G + 128)     // 57216, data 7680B
#define OY1F_LO_G (OY1F_HI + 7680)      // 64896
#define OY1F_LO   (OY1F_LO_G + 128)     // 65024, data 7680B
// A plane (y3 / y5): 192 rows x 176 B
#define OBA_HI (OY1F_LO + 7680)         // 72704
#define OBA_LO (OBA_HI + 33792)         // 106496
// B plane (y2 / y4): 192 rows x 112 B
#define OBB_HI (OBA_LO + 33792)         // 140288
#define OBB_LO (OBB_HI + 21504)         // 161792
#define ODIF   (OBB_LO + 21504)         // 183296 (196 f32 + guard)
#define SMEM_BYTES (ODIF + 1024)        // 184320

__device__ float g_bm[MAXN];

// ---------------- helpers ----------------
__device__ __forceinline__ u32 sm_u32(const void* p) {
    u32 a;
    asm("{ .reg .u64 t; cvta.to.shared.u64 t, %1; cvt.u32.u64 %0, t; }" : "=r"(a) : "l"(p));
    return a;
}
__device__ __forceinline__ void ldm4(u32 addr, u32& a0, u32& a1, u32& a2, u32& a3) {
    asm volatile("ldmatrix.sync.aligned.m8n8.x4.shared.b16 {%0,%1,%2,%3},[%4];"
                 : "=r"(a0), "=r"(a1), "=r"(a2), "=r"(a3) : "r"(addr));
}
__device__ __forceinline__ void ldm2(u32 addr, u32& a0, u32& a1) {
    asm volatile("ldmatrix.sync.aligned.m8n8.x2.shared.b16 {%0,%1},[%2];"
                 : "=r"(a0), "=r"(a1) : "r"(addr));
}
__device__ __forceinline__ u32 lds32(u32 a) {
    u32 v; asm volatile("ld.shared.u32 %0,[%1];" : "=r"(v) : "r"(a)); return v;
}
__device__ __forceinline__ void sts32(u32 a, u32 v) {
    asm volatile("st.shared.u32 [%0],%1;" :: "r"(a), "r"(v));
}
__device__ __forceinline__ void mma16816(float* d, u32 a0, u32 a1, u32 a2, u32 a3, u32 b0, u32 b1) {
    asm volatile("mma.sync.aligned.m16n8k16.row.col.f32.bf16.bf16.f32 "
                 "{%0,%1,%2,%3},{%4,%5,%6,%7},{%8,%9},{%0,%1,%2,%3};"
                 : "+f"(d[0]), "+f"(d[1]), "+f"(d[2]), "+f"(d[3])
                 : "r"(a0), "r"(a1), "r"(a2), "r"(a3), "r"(b0), "r"(b1));
}
__device__ __forceinline__ void mma16808(float* d, u32 a0, u32 a1, u32 b0) {
    asm volatile("mma.sync.aligned.m16n8k8.row.col.f32.bf16.bf16.f32 "
                 "{%0,%1,%2,%3},{%4,%5},{%6},{%0,%1,%2,%3};"
                 : "+f"(d[0]), "+f"(d[1]), "+f"(d[2]), "+f"(d[3])
                 : "r"(a0), "r"(a1), "r"(b0));
}
__device__ __forceinline__ float elu1(float x) {
    float e = __expf(x) - 1.0f;
    return x > 0.0f ? x : e;
}

// shared epilogue: bias + elu + kill + bf16 split + store
template<int NT, int BOFS, int RLO, int RHI>
__device__ __forceinline__ void epilogue(float acc[][4], u32 dstHi, u32 dstLo, int RSdst,
                                         const float* sc, int m0, int lane, int g0, int N)
{
    const int c = lane & 3, nrow = lane >> 2;
    #pragma unroll
    for (int nt = 0; nt < NT; nt++) {
        int nb = nt * 8 + 2 * c;
        float b0f = sc[BOFS + nb], b1f = sc[BOFS + nb + 1];
        #pragma unroll
        for (int j = 0; j < 2; j++) {
            int row = m0 + nrow + 8 * j;
            int p = g0 + row - 6;
            bool kill = (row < RLO) | (row >= RHI) | (p < 0) | (p >= N);
            float v0 = elu1(acc[nt][2 * j] + b0f);
            float v1 = elu1(acc[nt][2 * j + 1] + b1f);
            if (kill) { v0 = 0.f; v1 = 0.f; }
            __nv_bfloat162 hh = __floats2bfloat162_rn(v0, v1);
            float h0f = __bfloat162float(hh.x), h1f = __bfloat162float(hh.y);
            __nv_bfloat162 ll = __floats2bfloat162_rn(v0 - h0f, v1 - h1f);
            u32 off = (u32)(row * RSdst + nb * 2);
            sts32(dstHi + off, *(u32*)&hh);
            sts32(dstLo + off, *(u32*)&ll);
        }
    }
}

// ---------------- general MMA layer (ldmatrix A) with optional k8 tail ----------------
template<int TAPS, int PAD, int KC, int K8, int NT, int KP, int NR, int WOFS, int BOFS, int RLO, int RHI>
__device__ __forceinline__ void mma_layer(u32 smb, u32 srcHi, u32 srcLo, int RSsrc,
                                          u32 dstHi, u32 dstLo, int RSdst,
                                          const float* sc, int warp, int lane, int g0, int N)
{
    float acc[NT][4];
    #pragma unroll
    for (int i = 0; i < NT; i++) { acc[i][0] = acc[i][1] = acc[i][2] = acc[i][3] = 0.f; }
    const int m0 = warp * 16;
    const int r = lane & 15, half = lane >> 4;
    const int c = lane & 3, nrow = lane >> 2;
    const u32 wB = smb + OWHI;
    const u32 loDelta = srcLo - srcHi;
    const u32 wPlaneDelta = OWLO - OWHI;

    #pragma unroll
    for (int t = 0; t < TAPS; t++) {
        #pragma unroll
        for (int kc = 0; kc < KC; kc++) {
            u32 aad = srcHi + (u32)((m0 + r + t - PAD) * RSsrc) + kc * 32 + half * 16;
            u32 h0, h1, h2, h3, l0, l1, l2, l3;
            ldm4(aad, h0, h1, h2, h3);
            ldm4(aad + loDelta, l0, l1, l2, l3);
            #pragma unroll
            for (int nt = 0; nt < NT; nt++) {
                int n = nt * 8 + nrow;
                u32 wo = wB + (u32)((WOFS + (t * NR + n) * KP + kc * 16 + 2 * c) * 2);
                u32 bh0 = lds32(wo),               bh1 = lds32(wo + 16);
                u32 bl0 = lds32(wo + wPlaneDelta), bl1 = lds32(wo + wPlaneDelta + 16);
                mma16816(acc[nt], h0, h1, h2, h3, bh0, bh1);
                mma16816(acc[nt], l0, l1, l2, l3, bh0, bh1);
                mma16816(acc[nt], h0, h1, h2, h3, bl0, bl1);
            }
        }
        if (K8) {   // k8 tail at kb = KC*16
            u32 aad = srcHi + (u32)((m0 + r + t - PAD) * RSsrc) + KC * 32;
            u32 h0, h1, l0, l1;
            ldm2(aad, h0, h1);
            ldm2(aad + loDelta, l0, l1);
            #pragma unroll
            for (int nt = 0; nt < NT; nt++) {
                int n = nt * 8 + nrow;
                u32 wo = wB + (u32)((WOFS + (t * NR + n) * KP + KC * 16 + 2 * c) * 2);
                u32 bh = lds32(wo);
                u32 bl = lds32(wo + wPlaneDelta);
                mma16808(acc[nt], h0, h1, bh);
                mma16808(acc[nt], l0, l1, bh);
                mma16808(acc[nt], h0, h1, bl);
            }
        }
    }
    epilogue<NT, BOFS, RLO, RHI>(acc, dstHi, dstLo, RSdst, sc, m0, lane, g0, N);
}

// ---------------- L2: flat-im2col (A rows = y1f[(r-2)*20 + k], 40B stride) ----------------
__device__ __forceinline__ void mma_layer2(u32 smb, u32 dstHi, u32 dstLo,
                                           const float* sc, int warp, int lane, int g0, int N)
{
    float acc[5][4];
    #pragma unroll
    for (int i = 0; i < 5; i++) { acc[i][0] = acc[i][1] = acc[i][2] = acc[i][3] = 0.f; }
    const int m0 = warp * 16;
    const int c = lane & 3, nrow = lane >> 2;
    const int g = lane >> 2;
    const u32 wB = smb + OWHI;
    const u32 aH = smb + OY1F_HI;
    const int r0 = m0 + g, r1 = r0 + 8;
    // base byte offsets for the two A rows at k = 2c
    const u32 o0 = aH + (u32)((r0 - 2) * 40 + 4 * c);
    const u32 o1 = aH + (u32)((r1 - 2) * 40 + 4 * c);
    const u32 LOD = OY1F_LO - OY1F_HI;

    #pragma unroll
    for (int kc = 0; kc < 7; kc++) {
        u32 kb = kc * 32;   // byte offset of k-chunk
        u32 h0 = lds32(o0 + kb),        h1 = lds32(o1 + kb);
        u32 h2 = lds32(o0 + kb + 16),   h3 = lds32(o1 + kb + 16);
        u32 l0 = lds32(o0 + kb + LOD),      l1 = lds32(o1 + kb + LOD);
        u32 l2 = lds32(o0 + kb + 16 + LOD), l3 = lds32(o1 + kb + 16 + LOD);
        #pragma unroll
        for (int nt = 0; nt < 5; nt++) {
            int n = nt * 8 + nrow;
            u32 wo = wB + (u32)((PW2 + n * 112 + kc * 16 + 2 * c) * 2);
            u32 bh0 = lds32(wo),                    bh1 = lds32(wo + 16);
            u32 bl0 = lds32(wo + (OWLO - OWHI)),    bl1 = lds32(wo + (OWLO - OWHI) + 16);
            mma16816(acc[nt], h0, h1, h2, h3, bh0, bh1);
            mma16816(acc[nt], l0, l1, l2, l3, bh0, bh1);
            mma16816(acc[nt], h0, h1, h2, h3, bl0, bl1);
        }
    }
    epilogue<5, SB2, 4, 188>(acc, dstHi, dstLo, 112, sc, m0, lane, g0, N);
}

__global__ __launch_bounds__(NTHREADS, 1)
void cnn_kernel(const float* __restrict__ uu,
                const float* __restrict__ w1, const float* __restrict__ b1,
                const float* __restrict__ w2, const float* __restrict__ b2,
                const float* __restrict__ w3, const float* __restrict__ b3,
                const float* __restrict__ w4, const float* __restrict__ b4,
                const float* __restrict__ w5, const float* __restrict__ b5,
                const float* __restrict__ w6, const float* __restrict__ b6,
                int N, int nTiles)
{
    extern __shared__ unsigned char sm[];
    const int tid = threadIdx.x, lane = tid & 31, warp = tid >> 5;
    const u32 smb = sm_u32(sm);
    float* sc = (float*)(sm + OSC);
    __nv_bfloat16* WH = (__nv_bfloat16*)(sm + OWHI);
    __nv_bfloat16* WL = (__nv_bfloat16*)(sm + OWLO);
    float* dif = (float*)(sm + ODIF);
    __nv_bfloat16* y1h = (__nv_bfloat16*)(sm + OY1F_HI);
    __nv_bfloat16* y1l = (__nv_bfloat16*)(sm + OY1F_LO);
    __nv_bfloat16* bPh = (__nv_bfloat16*)(sm + OBA_HI);
    __nv_bfloat16* bPl = (__nv_bfloat16*)(sm + OBA_LO);

    // ---- scalars ----
    for (int i = tid; i < 100; i += NTHREADS) { int co = i / 5, t = i % 5; sc[SW1 + t * 20 + co] = w1[i]; }
    for (int i = tid; i < 20; i += NTHREADS) sc[SB1 + i] = b1[i];
    for (int i = tid; i < 40; i += NTHREADS) sc[SB2 + i] = b2[i];
    for (int i = tid; i < 80; i += NTHREADS) sc[SB3 + i] = b3[i];
    for (int i = tid; i < 40; i += NTHREADS) sc[SB4 + i] = b4[i];
    for (int i = tid; i < 24; i += NTHREADS) sc[SB5 + i] = (i < 20) ? b5[i] : 0.f;
    for (int i = tid; i < 20; i += NTHREADS) sc[SW6 + i] = w6[i];
    if (tid == 0) sc[SB6] = b6[0];

    // ---- weight planes (bf16 two-term split), zero-padded ----
    #define PUTW(idx, wv) do { float _w = (wv); __nv_bfloat16 _h = __float2bfloat16(_w); \
        WH[idx] = _h; WL[idx] = __float2bfloat16(_w - __bfloat162float(_h)); } while (0)
    for (int i = tid; i < 4480; i += NTHREADS) {         // W2 [40][112], K = t*20+ci
        int n = i / 112, k = i % 112;
        PUTW(PW2 + i, k < 100 ? w2[(n * 20 + k % 20) * 5 + k / 20] : 0.f);
    }
    for (int i = tid; i < 3200; i += NTHREADS) {         // W3 [80][40] exact
        int n = i / 40, ci = i % 40;
        PUTW(PW3 + i, w3[n * 40 + ci]);
    }
    for (int i = tid; i < 3360; i += NTHREADS) {         // W4 [40][84]
        int n = i / 84, ci = i % 84;
        PUTW(PW4 + i, ci < 80 ? w4[n * 80 + ci] : 0.f);
    }
    for (int i = tid; i < 2880; i += NTHREADS) {         // W5 [3][24][40]
        int t = i / 960, rr = i % 960, n = rr / 40, ci = rr % 40;
        PUTW(PW5 + i, (n < 20) ? w5[(n * 40 + ci) * 3 + t] : 0.f);
    }
    // zero activation buffers + y1f guards once
    {
        uint4* z = (uint4*)(sm + OY1F_HI_G);
        const int cnt = (SMEM_BYTES - 1024 - OY1F_HI_G) / 16;   // through OBB_LO end
        for (int i = tid; i < cnt; i += NTHREADS) z[i] = make_uint4(0, 0, 0, 0);
    }
    __syncthreads();

    const u32 BPH = smb + OBA_HI, BPL = smb + OBA_LO;
    const u32 BQH = smb + OBB_HI, BQL = smb + OBB_LO;

    for (int tile = blockIdx.x; tile < nTiles; tile += GRID_P) {
        const int g0 = tile * T;

        // ---- dif: idx 0..195 <-> lp = idx-8 ----
        for (int ld = tid; ld < 196; ld += NTHREADS) {
            int gd = g0 + ld - 8;
            float v = 0.f;
            if (gd >= 0 && gd < N) {
                if (gd == 0)          v = __ldg(&uu[1]) - __ldg(&uu[0]);
                else if (gd == N - 1) v = __ldg(&uu[N - 1]) - __ldg(&uu[N - 2]);
                else                  v = 0.5f * (__ldg(&uu[gd + 1]) - __ldg(&uu[gd - 1]));
            }
            dif[ld] = v;
        }
        __syncthreads();

        // ---- L1 scalar: 1->20 k5 pad2; row = lp+6, valid rows [2,190); dense y1f ----
        for (int i = tid; i < 3840; i += NTHREADS) {
            int row = i % 192, co = i / 192;
            float a = sc[SB1 + co];
            #pragma unroll
            for (int t = 0; t < 5; t++) a += sc[SW1 + t * 20 + co] * dif[row + t];
            int p = g0 + row - 6;
            float v = elu1(a);
            if (row < 2 || row >= 190 || p < 0 || p >= N) v = 0.f;
            __nv_bfloat16 h = __float2bfloat16(v);
            y1h[row * 20 + co] = h;
            y1l[row * 20 + co] = __float2bfloat16(v - __bfloat162float(h));
        }
        __syncthreads();

        // L2: 20->40 k5 via flat im2col | K=112 (100 real), rows [4,188) -> Q
        mma_layer2(smb, BQH, BQL, sc, warp, lane, g0, N);
        __syncthreads();
        // L3: 40->80 k1 | kc2 + k8 tail, KP40, NT10, rows [4,188); Q -> P (176B)
        mma_layer<1, 0, 2, 1, 10, 40, 80, PW3, SB3, 4, 188>(smb, BQH, BQL, 112, BPH, BPL, 176, sc, warp, lane, g0, N);
        __syncthreads();
        // L4: 80->40 k1 | kc5, KP84, NT5, rows [4,188); P -> Q
        mma_layer<1, 0, 5, 0, 5, 84, 40, PW4, SB4, 4, 188>(smb, BPH, BPL, 176, BQH, BQL, 112, sc, warp, lane, g0, N);
        __syncthreads();
        // L5: 40->20 k3 pad1 | per-tap kc2 + k8 tail, KP40, NT3, rows [6,186); Q -> P (176B)
        mma_layer<3, 1, 2, 1, 3, 40, 24, PW5, SB5, 6, 186>(smb, BQH, BQL, 112, BPH, BPL, 176, sc, warp, lane, g0, N);
        __syncthreads();

        // ---- L6: 20->1, sigmoid, +0.1 (reads y5 from P, stride 88 elems) ----
        for (int i = tid; i < T; i += NTHREADS) {
            int row = i + 6, p = g0 + i;
            if (p < N) {
                float a = sc[SB6];
                #pragma unroll
                for (int cch = 0; cch < 20; cch++)
                    a += sc[SW6 + cch] * (__bfloat162float(bPh[row * 88 + cch]) +
                                          __bfloat162float(bPl[row * 88 + cch]));
                g_bm[p] = 1.f / (1.f + __expf(-a)) + 0.1f;
            }
        }
        // next iteration's post-dif barrier provides ordering
    }
}

// ---------------- WENO reconstruction ----------------
__device__ __forceinline__ float weno_flux(float a, float b, float c, float d, float e,
                                           float bm_m1, float bm_0, float bm_p1)
{
    const float C1312 = 13.0f / 12.0f;
    const float E = 1e-13f;
    float f0 = (11.0f * c - 7.0f * d + 2.0f * e) * (1.0f / 6.0f);
    float f1 = (2.0f * b + 5.0f * c - d) * (1.0f / 6.0f);
    float f2 = (-a + 5.0f * b + 2.0f * c) * (1.0f / 6.0f);

    float t0a = c - 2.0f * d + e, t0b = 3.0f * c - 4.0f * d + e;
    float t1a = b - 2.0f * c + d, t1b = b - d;
    float t2a = a - 2.0f * b + c, t2b = a - 4.0f * b + 3.0f * c;
    float b0 = C1312 * t0a * t0a + 0.25f * t0b * t0b;
    float b1 = C1312 * t1a * t1a + 0.25f * t1b * t1b;
    float b2 = C1312 * t2a * t2a + 0.25f * t2b * t2b;

    b0 *= bm_p1;
    b1 *= bm_0;
    b2 *= bm_m1;

    float brs = (b2 - b0) * (b2 - b0);
    float e0 = (E + b0) * (E + b0);
    float e1 = (E + b1) * (E + b1);
    float e2 = (E + b2) * (E + b2);
    float om0 = 0.1f / e0 * (brs + e0);
    float om1 = 0.6f / e1 * (brs + e1);
    float om2 = 0.3f / e2 * (brs + e2);
    return (om0 * f0 + om1 * f1 + om2 * f2) / (om0 + om1 + om2);
}

__global__ void weno_kernel(const float* __restrict__ uu, float* __restrict__ out, int N)
{
    int i = blockIdx.x * blockDim.x + threadIdx.x;
    if (i >= N) return;
    int im2 = i - 2, im1 = i - 1, ip1 = i + 1, ip2 = i + 2, ip3 = i + 3;
    if (im2 < 0) im2 += N;
    if (im1 < 0) im1 += N;
    if (ip1 >= N) ip1 -= N;
    if (ip2 >= N) ip2 -= N;
    if (ip3 >= N) ip3 -= N;

    float umm = __ldg(&uu[im2]), um = __ldg(&uu[im1]), u0 = __ldg(&uu[i]);
    float up  = __ldg(&uu[ip1]), upp = __ldg(&uu[ip2]), uppp = __ldg(&uu[ip3]);
    float bm_m1 = g_bm[im1], bm_0 = g_bm[i], bm_p1 = g_bm[ip1];

    float fluxp = weno_flux(um, u0, up, upp, uppp, bm_m1, bm_0, bm_p1);
    float fluxn = weno_flux(umm, um, u0, up, upp, bm_m1, bm_0, bm_p1);

    out[i] = fluxp - fluxn;
}

extern "C" void kernel_launch(void* const* d_in, const int* in_sizes, int n_in,
                              void* d_out, int out_size)
{
    const float* uu = (const float*)d_in[0];
    const float* w1 = (const float*)d_in[1];
    const float* b1 = (const float*)d_in[2];
    const float* w2 = (const float*)d_in[3];
    const float* b2 = (const float*)d_in[4];
    const float* w3 = (const float*)d_in[5];
    const float* b3 = (const float*)d_in[6];
    const float* w4 = (const float*)d_in[7];
    const float* b4 = (const float*)d_in[8];
    const float* w5 = (const float*)d_in[9];
    const float* b5 = (const float*)d_in[10];
    const float* w6 = (const float*)d_in[11];
    const float* b6 = (const float*)d_in[12];
    float* out = (float*)d_out;
    int N = in_sizes[0];

    cudaFuncSetAttribute(cnn_kernel, cudaFuncAttributeMaxDynamicSharedMemorySize, SMEM_BYTES);

    int nTiles = (N + T - 1) / T;
    int grid = nTiles < GRID_P ? nTiles : GRID_P;
    cnn_kernel<<<grid, NTHREADS, SMEM_BYTES>>>(uu, w1, b1, w2, b2, w3, b3, w4, b4,
                                               w5, b5, w6, b6, N, nTiles);
    weno_kernel<<<(N + 255) / 256, 256>>>(uu, out, N);
}

// round 14
// speedup vs baseline: 1.8789x; 1.8789x over previous
#include <cuda_runtime.h>
#include <cuda_fp16.h>
#include <cstdint>

#define NTHREADS 384
#define T        180
#define GRID_P   152
#define MAXN     2097152

typedef unsigned int u32;

// ---- W plane element offsets (fp16 elems, hi only) ----
#define PW2 0          // [5][40][40]  = 8000
#define PW3 8000       // [80][56]     = 4480
#define PW4 12480      // [40][84]     = 3360
#define PW5 15840      // [3][24][56]  = 4032
#define PLANE_ELEMS 19872

// ---- smem byte offsets ----
#define OWHI 0
#define OSC  (PLANE_ELEMS*2)            // 39744 (f32 scalars, 325 floats)
#define SW1 0
#define SB1 100
#define SB2 120
#define SB3 160
#define SB4 240
#define SB5 280      // 24 (20 real + 4 zero)
#define SW6 304
#define SB6 324
#define OBA_HI 41472                    // bufA hi: 192*176 = 33792 B
#define OBA_LO (OBA_HI+33792)           // 75264
#define OBB_HI (OBA_LO+33792)           // 109056 bufB hi: 192*112 = 21504 B
#define OBB_LO (OBB_HI+21504)           // 130560
#define ODIF   (OBB_LO+21504)           // 152064 (196 f32 + guard)
#define SMEM_BYTES (ODIF + 1024)        // 153088

__device__ float g_bm[MAXN];

// ---------------- helpers ----------------
__device__ __forceinline__ u32 sm_u32(const void* p) {
    u32 a;
    asm("{ .reg .u64 t; cvta.to.shared.u64 t, %1; cvt.u32.u64 %0, t; }" : "=r"(a) : "l"(p));
    return a;
}
__device__ __forceinline__ void ldm4(u32 addr, u32& a0, u32& a1, u32& a2, u32& a3) {
    asm volatile("ldmatrix.sync.aligned.m8n8.x4.shared.b16 {%0,%1,%2,%3},[%4];"
                 : "=r"(a0), "=r"(a1), "=r"(a2), "=r"(a3) : "r"(addr));
}
__device__ __forceinline__ u32 lds32(u32 a) {
    u32 v; asm volatile("ld.shared.u32 %0,[%1];" : "=r"(v) : "r"(a)); return v;
}
__device__ __forceinline__ void sts32(u32 a, u32 v) {
    asm volatile("st.shared.u32 [%0],%1;" :: "r"(a), "r"(v));
}
__device__ __forceinline__ void mma16816(float* d, u32 a0, u32 a1, u32 a2, u32 a3, u32 b0, u32 b1) {
    asm volatile("mma.sync.aligned.m16n8k16.row.col.f32.f16.f16.f32 "
                 "{%0,%1,%2,%3},{%4,%5,%6,%7},{%8,%9},{%0,%1,%2,%3};"
                 : "+f"(d[0]), "+f"(d[1]), "+f"(d[2]), "+f"(d[3])
                 : "r"(a0), "r"(a1), "r"(a2), "r"(a3), "r"(b0), "r"(b1));
}
__device__ __forceinline__ float elu1(float x) {
    float e = __expf(x) - 1.0f;
    return x > 0.0f ? x : e;
}

// ---------------- MMA conv layer ----------------
// A rows = positions (row index = lp+6), cols = cin (fp16 hi/lo planes).
// W[t][n][KP] fp16 (hi only), B-frag b0={k=2c,2c+1}@n, b1={k=2c+8,2c+9}@n.
// D = Ahi*B + Alo*B = A*B with fp16-quantized weights.
template<int TAPS, int PAD, int KC, int NT, int KP, int NR, int WOFS, int BOFS, int RLO, int RHI>
__device__ __forceinline__ void mma_layer(u32 smb, u32 srcHi, u32 srcLo, int RSsrc,
                                          u32 dstHi, u32 dstLo, int RSdst,
                                          const float* sc, int warp, int lane, int g0, int N)
{
    float acc[NT][4];
    #pragma unroll
    for (int i = 0; i < NT; i++) { acc[i][0] = acc[i][1] = acc[i][2] = acc[i][3] = 0.f; }
    const int m0 = warp * 16;
    const int r = lane & 15, half = lane >> 4;
    const int c = lane & 3, nrow = lane >> 2;
    const u32 wB = smb + OWHI;
    const u32 loDelta = srcLo - srcHi;

    #pragma unroll
    for (int t = 0; t < TAPS; t++) {
        #pragma unroll
        for (int kc = 0; kc < KC; kc++) {
            u32 aad = srcHi + (u32)((m0 + r + t - PAD) * RSsrc) + kc * 32 + half * 16;
            u32 h0, h1, h2, h3, l0, l1, l2, l3;
            ldm4(aad, h0, h1, h2, h3);
            ldm4(aad + loDelta, l0, l1, l2, l3);
            #pragma unroll
            for (int nt = 0; nt < NT; nt++) {
                int n = nt * 8 + nrow;
                u32 wo = wB + (u32)((WOFS + (t * NR + n) * KP + kc * 16 + 2 * c) * 2);
                u32 bh0 = lds32(wo), bh1 = lds32(wo + 16);
                mma16816(acc[nt], h0, h1, h2, h3, bh0, bh1);
                mma16816(acc[nt], l0, l1, l2, l3, bh0, bh1);
            }
        }
    }
    // epilogue: bias + elu + kill + fp16 split + store
    #pragma unroll
    for (int nt = 0; nt < NT; nt++) {
        int nb = nt * 8 + 2 * c;
        float b0f = sc[BOFS + nb], b1f = sc[BOFS + nb + 1];
        #pragma unroll
        for (int j = 0; j < 2; j++) {
            int row = m0 + nrow + 8 * j;
            int p = g0 + row - 6;
            bool kill = (row < RLO) | (row >= RHI) | (p < 0) | (p >= N);
            float v0 = elu1(acc[nt][2 * j] + b0f);
            float v1 = elu1(acc[nt][2 * j + 1] + b1f);
            if (kill) { v0 = 0.f; v1 = 0.f; }
            __half2 hh = __floats2half2_rn(v0, v1);
            float h0f = __half2float(__low2half(hh)), h1f = __half2float(__high2half(hh));
            __half2 ll = __floats2half2_rn(v0 - h0f, v1 - h1f);
            u32 off = (u32)(row * RSdst + nb * 2);
            sts32(dstHi + off, *(u32*)&hh);
            sts32(dstLo + off, *(u32*)&ll);
        }
    }
}

__global__ __launch_bounds__(NTHREADS, 1)
void cnn_kernel(const float* __restrict__ uu,
                const float* __restrict__ w1, const float* __restrict__ b1,
                const float* __restrict__ w2, const float* __restrict__ b2,
                const float* __restrict__ w3, const float* __restrict__ b3,
                const float* __restrict__ w4, const float* __restrict__ b4,
                const float* __restrict__ w5, const float* __restrict__ b5,
                const float* __restrict__ w6, const float* __restrict__ b6,
                int N, int nTiles)
{
    extern __shared__ unsigned char sm[];
    const int tid = threadIdx.x, lane = tid & 31, warp = tid >> 5;
    const u32 smb = sm_u32(sm);
    float* sc = (float*)(sm + OSC);
    __half* WH = (__half*)(sm + OWHI);
    float* dif = (float*)(sm + ODIF);
    __half* bAh = (__half*)(sm + OBA_HI);
    __half* bAl = (__half*)(sm + OBA_LO);

    // ---- scalars ----
    for (int i = tid; i < 100; i += NTHREADS) { int co = i / 5, t = i % 5; sc[SW1 + t * 20 + co] = w1[i]; }
    for (int i = tid; i < 20; i += NTHREADS) sc[SB1 + i] = b1[i];
    for (int i = tid; i < 40; i += NTHREADS) sc[SB2 + i] = b2[i];
    for (int i = tid; i < 80; i += NTHREADS) sc[SB3 + i] = b3[i];
    for (int i = tid; i < 40; i += NTHREADS) sc[SB4 + i] = b4[i];
    for (int i = tid; i < 24; i += NTHREADS) sc[SB5 + i] = (i < 20) ? b5[i] : 0.f;
    for (int i = tid; i < 20; i += NTHREADS) sc[SW6 + i] = w6[i];
    if (tid == 0) sc[SB6] = b6[0];

    // ---- weight planes (fp16), zero-padded ----
    #define PUTW(idx, wv) do { WH[idx] = __float2half_rn(wv); } while (0)
    for (int i = tid; i < 8000; i += NTHREADS) {         // W2 [5][40][40]
        int t = i / 1600, rr = i % 1600, n = rr / 40, ci = rr % 40;
        PUTW(PW2 + i, ci < 20 ? w2[(n * 20 + ci) * 5 + t] : 0.f);
    }
    for (int i = tid; i < 4480; i += NTHREADS) {         // W3 [80][56]
        int n = i / 56, ci = i % 56;
        PUTW(PW3 + i, ci < 40 ? w3[n * 40 + ci] : 0.f);
    }
    for (int i = tid; i < 3360; i += NTHREADS) {         // W4 [40][84]
        int n = i / 84, ci = i % 84;
        PUTW(PW4 + i, ci < 80 ? w4[n * 80 + ci] : 0.f);
    }
    for (int i = tid; i < 4032; i += NTHREADS) {         // W5 [3][24][56]
        int t = i / 1344, rr = i % 1344, n = rr / 56, ci = rr % 56;
        PUTW(PW5 + i, (n < 20 && ci < 40) ? w5[(n * 40 + ci) * 3 + t] : 0.f);
    }
    // zero activation buffers (once; padded cols stay finite/zero)
    {
        uint4* z = (uint4*)(sm + OBA_HI);
        const int cnt = (33792 * 2 + 21504 * 2) / 16;
        for (int i = tid; i < cnt; i += NTHREADS) z[i] = make_uint4(0, 0, 0, 0);
    }
    __syncthreads();

    const u32 BAH = smb + OBA_HI, BAL = smb + OBA_LO;
    const u32 BBH = smb + OBB_HI, BBL = smb + OBB_LO;

    for (int tile = blockIdx.x; tile < nTiles; tile += GRID_P) {
        const int g0 = tile * T;

        // ---- dif: idx 0..195 <-> lp = idx-8 ----
        for (int ld = tid; ld < 196; ld += NTHREADS) {
            int gd = g0 + ld - 8;
            float v = 0.f;
            if (gd >= 0 && gd < N) {
                if (gd == 0)          v = __ldg(&uu[1]) - __ldg(&uu[0]);
                else if (gd == N - 1) v = __ldg(&uu[N - 1]) - __ldg(&uu[N - 2]);
                else                  v = 0.5f * (__ldg(&uu[gd + 1]) - __ldg(&uu[gd - 1]));
            }
            dif[ld] = v;
        }
        __syncthreads();   // also orders prev-tile L6 reads before L1 writes

        // ---- L1 scalar: 1->20 k5 pad2; row = lp+6, valid rows [2,190) ----
        for (int i = tid; i < 3840; i += NTHREADS) {
            int row = i % 192, co = i / 192;
            float a = sc[SB1 + co];
            #pragma unroll
            for (int t = 0; t < 5; t++) a += sc[SW1 + t * 20 + co] * dif[row + t];
            int p = g0 + row - 6;
            float v = elu1(a);
            if (row < 2 || row >= 190 || p < 0 || p >= N) v = 0.f;
            __half h = __float2half_rn(v);
            bAh[row * 88 + co] = h;
            bAl[row * 88 + co] = __float2half_rn(v - __half2float(h));
        }
        __syncthreads();

        // L2: 20->40 k5 pad2 | taps5 kc2 NT5 KP40 NR40, rows [4,188)
        mma_layer<5, 2, 2, 5, 40, 40, PW2, SB2, 4, 188>(smb, BAH, BAL, 176, BBH, BBL, 112, sc, warp, lane, g0, N);
        __syncthreads();
        // L3: 40->80 k1 | kc3 NT10 KP56, rows [4,188)
        mma_layer<1, 0, 3, 10, 56, 80, PW3, SB3, 4, 188>(smb, BBH, BBL, 112, BAH, BAL, 176, sc, warp, lane, g0, N);
        __syncthreads();
        // L4: 80->40 k1 | kc5 NT5 KP84, rows [4,188)
        mma_layer<1, 0, 5, 5, 84, 40, PW4, SB4, 4, 188>(smb, BAH, BAL, 176, BBH, BBL, 112, sc, warp, lane, g0, N);
        __syncthreads();
        // L5: 40->20 k3 pad1 | taps3 kc3 NT3 KP56 NR24, rows [6,186)
        mma_layer<3, 1, 3, 3, 56, 24, PW5, SB5, 6, 186>(smb, BBH, BBL, 112, BAH, BAL, 176, sc, warp, lane, g0, N);
        __syncthreads();

        // ---- L6: 20->1, sigmoid, +0.1 ----
        for (int i = tid; i < T; i += NTHREADS) {
            int row = i + 6, p = g0 + i;
            if (p < N) {
                float a = sc[SB6];
                #pragma unroll
                for (int cch = 0; cch < 20; cch++)
                    a += sc[SW6 + cch] * (__half2float(bAh[row * 88 + cch]) +
                                          __half2float(bAl[row * 88 + cch]));
                g_bm[p] = 1.f / (1.f + __expf(-a)) + 0.1f;
            }
        }
        // next iteration's post-dif barrier provides ordering
    }
}

// ---------------- WENO reconstruction ----------------
__device__ __forceinline__ float weno_flux(float a, float b, float c, float d, float e,
                                           float bm_m1, float bm_0, float bm_p1)
{
    const float C1312 = 13.0f / 12.0f;
    const float E = 1e-13f;
    float f0 = (11.0f * c - 7.0f * d + 2.0f * e) * (1.0f / 6.0f);
    float f1 = (2.0f * b + 5.0f * c - d) * (1.0f / 6.0f);
    float f2 = (-a + 5.0f * b + 2.0f * c) * (1.0f / 6.0f);

    float t0a = c - 2.0f * d + e, t0b = 3.0f * c - 4.0f * d + e;
    float t1a = b - 2.0f * c + d, t1b = b - d;
    float t2a = a - 2.0f * b + c, t2b = a - 4.0f * b + 3.0f * c;
    float b0 = C1312 * t0a * t0a + 0.25f * t0b * t0b;
    float b1 = C1312 * t1a * t1a + 0.25f * t1b * t1b;
    float b2 = C1312 * t2a * t2a + 0.25f * t2b * t2b;

    b0 *= bm_p1;
    b1 *= bm_0;
    b2 *= bm_m1;

    float brs = (b2 - b0) * (b2 - b0);
    float e0 = (E + b0) * (E + b0);
    float e1 = (E + b1) * (E + b1);
    float e2 = (E + b2) * (E + b2);
    float om0 = 0.1f / e0 * (brs + e0);
    float om1 = 0.6f / e1 * (brs + e1);
    float om2 = 0.3f / e2 * (brs + e2);
    return (om0 * f0 + om1 * f1 + om2 * f2) / (om0 + om1 + om2);
}

__global__ void weno_kernel(const float* __restrict__ uu, float* __restrict__ out, int N)
{
    int i = blockIdx.x * blockDim.x + threadIdx.x;
    if (i >= N) return;
    int im2 = i - 2, im1 = i - 1, ip1 = i + 1, ip2 = i + 2, ip3 = i + 3;
    if (im2 < 0) im2 += N;
    if (im1 < 0) im1 += N;
    if (ip1 >= N) ip1 -= N;
    if (ip2 >= N) ip2 -= N;
    if (ip3 >= N) ip3 -= N;

    float umm = __ldg(&uu[im2]), um = __ldg(&uu[im1]), u0 = __ldg(&uu[i]);
    float up  = __ldg(&uu[ip1]), upp = __ldg(&uu[ip2]), uppp = __ldg(&uu[ip3]);
    float bm_m1 = g_bm[im1], bm_0 = g_bm[i], bm_p1 = g_bm[ip1];

    float fluxp = weno_flux(um, u0, up, upp, uppp, bm_m1, bm_0, bm_p1);
    float fluxn = weno_flux(umm, um, u0, up, upp, bm_m1, bm_0, bm_p1);

    out[i] = fluxp - fluxn;
}

extern "C" void kernel_launch(void* const* d_in, const int* in_sizes, int n_in,
                              void* d_out, int out_size)
{
    const float* uu = (const float*)d_in[0];
    const float* w1 = (const float*)d_in[1];
    const float* b1 = (const float*)d_in[2];
    const float* w2 = (const float*)d_in[3];
    const float* b2 = (const float*)d_in[4];
    const float* w3 = (const float*)d_in[5];
    const float* b3 = (const float*)d_in[6];
    const float* w4 = (const float*)d_in[7];
    const float* b4 = (const float*)d_in[8];
    const float* w5 = (const float*)d_in[9];
    const float* b5 = (const float*)d_in[10];
    const float* w6 = (const float*)d_in[11];
    const float* b6 = (const float*)d_in[12];
    float* out = (float*)d_out;
    int N = in_sizes[0];

    cudaFuncSetAttribute(cnn_kernel, cudaFuncAttributeMaxDynamicSharedMemorySize, SMEM_BYTES);

    int nTiles = (N + T - 1) / T;
    int grid = nTiles < GRID_P ? nTiles : GRID_P;
    cnn_kernel<<<grid, NTHREADS, SMEM_BYTES>>>(uu, w1, b1, w2, b2, w3, b3, w4, b4,
                                               w5, b5, w6, b6, N, nTiles);
    weno_kernel<<<(N + 255) / 256, 256>>>(uu, out, N);
}

// round 15
// speedup vs baseline: 2.9757x; 1.5837x over previous
#include <cuda_runtime.h>
#include <cuda_fp16.h>
#include <cstdint>

#define NTHREADS 384
#define T        180
#define GRID_P   304
#define MAXN     2097152

typedef unsigned int u32;

// ---- W plane element offsets (fp16 elems) ----
#define PW2 0          // [5][40][40]  = 8000
#define PW3 8000       // [80][56]     = 4480
#define PW4 12480      // [40][84]     = 3360
#define PW5 15840      // [3][24][56]  = 4032
#define PLANE_ELEMS 19872

// ---- smem byte offsets ----
#define OWHI 0
#define OSC  (PLANE_ELEMS*2)            // 39744 (f32 scalars, 325 floats)
#define SW1 0
#define SB1 100
#define SB2 120
#define SB3 160
#define SB4 240
#define SB5 280      // 24 (20 real + 4 zero)
#define SW6 304
#define SB6 324
#define OBA 41472                       // bufA: 192*176 = 33792 B (y1/y3/y5)
#define OBB (OBA+33792)                 // 75264  bufB: 192*112 = 21504 B (y2/y4)
#define ODIF (OBB+21504)                // 96768 (196 f32 + guard)
#define SMEM_BYTES (ODIF + 1024)        // 97792  -> 2 CTAs/SM

__device__ float g_bm[MAXN];

// ---------------- helpers ----------------
__device__ __forceinline__ u32 sm_u32(const void* p) {
    u32 a;
    asm("{ .reg .u64 t; cvta.to.shared.u64 t, %1; cvt.u32.u64 %0, t; }" : "=r"(a) : "l"(p));
    return a;
}
__device__ __forceinline__ void ldm4(u32 addr, u32& a0, u32& a1, u32& a2, u32& a3) {
    asm volatile("ldmatrix.sync.aligned.m8n8.x4.shared.b16 {%0,%1,%2,%3},[%4];"
                 : "=r"(a0), "=r"(a1), "=r"(a2), "=r"(a3) : "r"(addr));
}
__device__ __forceinline__ u32 lds32(u32 a) {
    u32 v; asm volatile("ld.shared.u32 %0,[%1];" : "=r"(v) : "r"(a)); return v;
}
__device__ __forceinline__ void sts32(u32 a, u32 v) {
    asm volatile("st.shared.u32 [%0],%1;" :: "r"(a), "r"(v));
}
__device__ __forceinline__ void mma16816(float* d, u32 a0, u32 a1, u32 a2, u32 a3, u32 b0, u32 b1) {
    asm volatile("mma.sync.aligned.m16n8k16.row.col.f32.f16.f16.f32 "
                 "{%0,%1,%2,%3},{%4,%5,%6,%7},{%8,%9},{%0,%1,%2,%3};"
                 : "+f"(d[0]), "+f"(d[1]), "+f"(d[2]), "+f"(d[3])
                 : "r"(a0), "r"(a1), "r"(a2), "r"(a3), "r"(b0), "r"(b1));
}
__device__ __forceinline__ float elu1(float x) {
    float e = __expf(x) - 1.0f;
    return x > 0.0f ? x : e;
}

// ---------------- MMA conv layer (single-term fp16) ----------------
// A rows = positions (row index = lp+6), cols = cin (fp16).
// W[t][n][KP] fp16, B-frag b0={k=2c,2c+1}@n, b1={k=2c+8,2c+9}@n.
template<int TAPS, int PAD, int KC, int NT, int KP, int NR, int WOFS, int BOFS, int RLO, int RHI>
__device__ __forceinline__ void mma_layer(u32 smb, u32 src, int RSsrc,
                                          u32 dst, int RSdst,
                                          const float* sc, int warp, int lane, int g0, int N)
{
    float acc[NT][4];
    #pragma unroll
    for (int i = 0; i < NT; i++) { acc[i][0] = acc[i][1] = acc[i][2] = acc[i][3] = 0.f; }
    const int m0 = warp * 16;
    const int r = lane & 15, half = lane >> 4;
    const int c = lane & 3, nrow = lane >> 2;
    const u32 wB = smb + OWHI;

    #pragma unroll
    for (int t = 0; t < TAPS; t++) {
        #pragma unroll
        for (int kc = 0; kc < KC; kc++) {
            u32 aad = src + (u32)((m0 + r + t - PAD) * RSsrc) + kc * 32 + half * 16;
            u32 h0, h1, h2, h3;
            ldm4(aad, h0, h1, h2, h3);
            #pragma unroll
            for (int nt = 0; nt < NT; nt++) {
                int n = nt * 8 + nrow;
                u32 wo = wB + (u32)((WOFS + (t * NR + n) * KP + kc * 16 + 2 * c) * 2);
                u32 bh0 = lds32(wo), bh1 = lds32(wo + 16);
                mma16816(acc[nt], h0, h1, h2, h3, bh0, bh1);
            }
        }
    }
    // epilogue: bias + elu + kill + fp16 store
    #pragma unroll
    for (int nt = 0; nt < NT; nt++) {
        int nb = nt * 8 + 2 * c;
        float b0f = sc[BOFS + nb], b1f = sc[BOFS + nb + 1];
        #pragma unroll
        for (int j = 0; j < 2; j++) {
            int row = m0 + nrow + 8 * j;
            int p = g0 + row - 6;
            bool kill = (row < RLO) | (row >= RHI) | (p < 0) | (p >= N);
            float v0 = elu1(acc[nt][2 * j] + b0f);
            float v1 = elu1(acc[nt][2 * j + 1] + b1f);
            if (kill) { v0 = 0.f; v1 = 0.f; }
            __half2 hh = __floats2half2_rn(v0, v1);
            sts32(dst + (u32)(row * RSdst + nb * 2), *(u32*)&hh);
        }
    }
}

__global__ __launch_bounds__(NTHREADS, 2)
void cnn_kernel(const float* __restrict__ uu,
                const float* __restrict__ w1, const float* __restrict__ b1,
                const float* __restrict__ w2, const float* __restrict__ b2,
                const float* __restrict__ w3, const float* __restrict__ b3,
                const float* __restrict__ w4, const float* __restrict__ b4,
                const float* __restrict__ w5, const float* __restrict__ b5,
                const float* __restrict__ w6, const float* __restrict__ b6,
                int N, int nTiles)
{
    extern __shared__ unsigned char sm[];
    const int tid = threadIdx.x, lane = tid & 31, warp = tid >> 5;
    const u32 smb = sm_u32(sm);
    float* sc = (float*)(sm + OSC);
    __half* WH = (__half*)(sm + OWHI);
    float* dif = (float*)(sm + ODIF);
    __half* bA = (__half*)(sm + OBA);

    // ---- scalars ----
    for (int i = tid; i < 100; i += NTHREADS) { int co = i / 5, t = i % 5; sc[SW1 + t * 20 + co] = w1[i]; }
    for (int i = tid; i < 20; i += NTHREADS) sc[SB1 + i] = b1[i];
    for (int i = tid; i < 40; i += NTHREADS) sc[SB2 + i] = b2[i];
    for (int i = tid; i < 80; i += NTHREADS) sc[SB3 + i] = b3[i];
    for (int i = tid; i < 40; i += NTHREADS) sc[SB4 + i] = b4[i];
    for (int i = tid; i < 24; i += NTHREADS) sc[SB5 + i] = (i < 20) ? b5[i] : 0.f;
    for (int i = tid; i < 20; i += NTHREADS) sc[SW6 + i] = w6[i];
    if (tid == 0) sc[SB6] = b6[0];

    // ---- weight planes (fp16), zero-padded ----
    #define PUTW(idx, wv) do { WH[idx] = __float2half_rn(wv); } while (0)
    for (int i = tid; i < 8000; i += NTHREADS) {         // W2 [5][40][40]
        int t = i / 1600, rr = i % 1600, n = rr / 40, ci = rr % 40;
        PUTW(PW2 + i, ci < 20 ? w2[(n * 20 + ci) * 5 + t] : 0.f);
    }
    for (int i = tid; i < 4480; i += NTHREADS) {         // W3 [80][56]
        int n = i / 56, ci = i % 56;
        PUTW(PW3 + i, ci < 40 ? w3[n * 40 + ci] : 0.f);
    }
    for (int i = tid; i < 3360; i += NTHREADS) {         // W4 [40][84]
        int n = i / 84, ci = i % 84;
        PUTW(PW4 + i, ci < 80 ? w4[n * 80 + ci] : 0.f);
    }
    for (int i = tid; i < 4032; i += NTHREADS) {         // W5 [3][24][56]
        int t = i / 1344, rr = i % 1344, n = rr / 56, ci = rr % 56;
        PUTW(PW5 + i, (n < 20 && ci < 40) ? w5[(n * 40 + ci) * 3 + t] : 0.f);
    }
    // zero activation buffers (once; padded cols stay finite/zero)
    {
        uint4* z = (uint4*)(sm + OBA);
        const int cnt = (33792 + 21504) / 16;
        for (int i = tid; i < cnt; i += NTHREADS) z[i] = make_uint4(0, 0, 0, 0);
    }
    __syncthreads();

    const u32 BA = smb + OBA, BB = smb + OBB;

    for (int tile = blockIdx.x; tile < nTiles; tile += GRID_P) {
        const int g0 = tile * T;

        // ---- dif: idx 0..195 <-> lp = idx-8 ----
        for (int ld = tid; ld < 196; ld += NTHREADS) {
            int gd = g0 + ld - 8;
            float v = 0.f;
            if (gd >= 0 && gd < N) {
                if (gd == 0)          v = __ldg(&uu[1]) - __ldg(&uu[0]);
                else if (gd == N - 1) v = __ldg(&uu[N - 1]) - __ldg(&uu[N - 2]);
                else                  v = 0.5f * (__ldg(&uu[gd + 1]) - __ldg(&uu[gd - 1]));
            }
            dif[ld] = v;
        }
        __syncthreads();   // also orders prev-tile L6 reads before L1 writes

        // ---- L1 scalar: 1->20 k5 pad2; row = lp+6, valid rows [2,190) ----
        for (int i = tid; i < 3840; i += NTHREADS) {
            int row = i % 192, co = i / 192;
            float a = sc[SB1 + co];
            #pragma unroll
            for (int t = 0; t < 5; t++) a += sc[SW1 + t * 20 + co] * dif[row + t];
            int p = g0 + row - 6;
            float v = elu1(a);
            if (row < 2 || row >= 190 || p < 0 || p >= N) v = 0.f;
            bA[row * 88 + co] = __float2half_rn(v);
        }
        __syncthreads();

        // L2: 20->40 k5 pad2 | taps5 kc2 NT5 KP40 NR40, rows [4,188)
        mma_layer<5, 2, 2, 5, 40, 40, PW2, SB2, 4, 188>(smb, BA, 176, BB, 112, sc, warp, lane, g0, N);
        __syncthreads();
        // L3: 40->80 k1 | kc3 NT10 KP56, rows [4,188)
        mma_layer<1, 0, 3, 10, 56, 80, PW3, SB3, 4, 188>(smb, BB, 112, BA, 176, sc, warp, lane, g0, N);
        __syncthreads();
        // L4: 80->40 k1 | kc5 NT5 KP84, rows [4,188)
        mma_layer<1, 0, 5, 5, 84, 40, PW4, SB4, 4, 188>(smb, BA, 176, BB, 112, sc, warp, lane, g0, N);
        __syncthreads();
        // L5: 40->20 k3 pad1 | taps3 kc3 NT3 KP56 NR24, rows [6,186)
        mma_layer<3, 1, 3, 3, 56, 24, PW5, SB5, 6, 186>(smb, BB, 112, BA, 176, sc, warp, lane, g0, N);
        __syncthreads();

        // ---- L6: 20->1, sigmoid, +0.1 ----
        for (int i = tid; i < T; i += NTHREADS) {
            int row = i + 6, p = g0 + i;
            if (p < N) {
                float a = sc[SB6];
                #pragma unroll
                for (int cch = 0; cch < 20; cch++)
                    a += sc[SW6 + cch] * __half2float(bA[row * 88 + cch]);
                g_bm[p] = 1.f / (1.f + __expf(-a)) + 0.1f;
            }
        }
        // next iteration's post-dif barrier provides ordering
    }
}

// ---------------- WENO reconstruction ----------------
__device__ __forceinline__ float weno_flux(float a, float b, float c, float d, float e,
                                           float bm_m1, float bm_0, float bm_p1)
{
    const float C1312 = 13.0f / 12.0f;
    const float E = 1e-13f;
    float f0 = (11.0f * c - 7.0f * d + 2.0f * e) * (1.0f / 6.0f);
    float f1 = (2.0f * b + 5.0f * c - d) * (1.0f / 6.0f);
    float f2 = (-a + 5.0f * b + 2.0f * c) * (1.0f / 6.0f);

    float t0a = c - 2.0f * d + e, t0b = 3.0f * c - 4.0f * d + e;
    float t1a = b - 2.0f * c + d, t1b = b - d;
    float t2a = a - 2.0f * b + c, t2b = a - 4.0f * b + 3.0f * c;
    float b0 = C1312 * t0a * t0a + 0.25f * t0b * t0b;
    float b1 = C1312 * t1a * t1a + 0.25f * t1b * t1b;
    float b2 = C1312 * t2a * t2a + 0.25f * t2b * t2b;

    b0 *= bm_p1;
    b1 *= bm_0;
    b2 *= bm_m1;

    float brs = (b2 - b0) * (b2 - b0);
    float e0 = (E + b0) * (E + b0);
    float e1 = (E + b1) * (E + b1);
    float e2 = (E + b2) * (E + b2);
    float om0 = 0.1f / e0 * (brs + e0);
    float om1 = 0.6f / e1 * (brs + e1);
    float om2 = 0.3f / e2 * (brs + e2);
    return (om0 * f0 + om1 * f1 + om2 * f2) / (om0 + om1 + om2);
}

__global__ void weno_kernel(const float* __restrict__ uu, float* __restrict__ out, int N)
{
    int i = blockIdx.x * blockDim.x + threadIdx.x;
    if (i >= N) return;
    int im2 = i - 2, im1 = i - 1, ip1 = i + 1, ip2 = i + 2, ip3 = i + 3;
    if (im2 < 0) im2 += N;
    if (im1 < 0) im1 += N;
    if (ip1 >= N) ip1 -= N;
    if (ip2 >= N) ip2 -= N;
    if (ip3 >= N) ip3 -= N;

    float umm = __ldg(&uu[im2]), um = __ldg(&uu[im1]), u0 = __ldg(&uu[i]);
    float up  = __ldg(&uu[ip1]), upp = __ldg(&uu[ip2]), uppp = __ldg(&uu[ip3]);
    float bm_m1 = g_bm[im1], bm_0 = g_bm[i], bm_p1 = g_bm[ip1];

    float fluxp = weno_flux(um, u0, up, upp, uppp, bm_m1, bm_0, bm_p1);
    float fluxn = weno_flux(umm, um, u0, up, upp, bm_m1, bm_0, bm_p1);

    out[i] = fluxp - fluxn;
}

extern "C" void kernel_launch(void* const* d_in, const int* in_sizes, int n_in,
                              void* d_out, int out_size)
{
    const float* uu = (const float*)d_in[0];
    const float* w1 = (const float*)d_in[1];
    const float* b1 = (const float*)d_in[2];
    const float* w2 = (const float*)d_in[3];
    const float* b2 = (const float*)d_in[4];
    const float* w3 = (const float*)d_in[5];
    const float* b3 = (const float*)d_in[6];
    const float* w4 = (const float*)d_in[7];
    const float* b4 = (const float*)d_in[8];
    const float* w5 = (const float*)d_in[9];
    const float* b5 = (const float*)d_in[10];
    const float* w6 = (const float*)d_in[11];
    const float* b6 = (const float*)d_in[12];
    float* out = (float*)d_out;
    int N = in_sizes[0];

    cudaFuncSetAttribute(cnn_kernel, cudaFuncAttributeMaxDynamicSharedMemorySize, SMEM_BYTES);

    int nTiles = (N + T - 1) / T;
    int grid = nTiles < GRID_P ? nTiles : GRID_P;
    cnn_kernel<<<grid, NTHREADS, SMEM_BYTES>>>(uu, w1, b1, w2, b2, w3, b3, w4, b4,
                                               w5, b5, w6, b6, N, nTiles);
    weno_kernel<<<(N + 255) / 256, 256>>>(uu, out, N);
}